// round 9
// baseline (speedup 1.0000x reference)
#include <cuda_runtime.h>
#include <cuda_fp16.h>
#include <cstdint>

#define D 128
#define AA 5
#define SS 4
#define MAXN 50000
#define MAXE 640000

// ---------------- static scratch (no runtime allocation allowed) ----------------
__device__ float    g_nx[(size_t)MAXN * D];              // node_x
__device__ float    g_wav[SS][(size_t)MAXN * D];         // fp32 wav levels 0..3 (self-term chain)
__device__ __half   g_wavh[SS + 1][(size_t)MAXN * D];    // fp16 levels 0..4 (gather + GEMM A)
__device__ unsigned g_w1p[256 * 256];                    // W1 packed half2-along-k, scales folded
__device__ unsigned g_w2p[128 * 128];                    // W2 packed half2-along-k
__device__ unsigned g_hp[(size_t)MAXN * 128];            // hidden packed half2 [N, 256 halves]
__device__ float    g_p[MAXN * AA];
__device__ float    g_q[MAXN * AA];
__device__ float    g_c[MAXN * AA];
__device__ int      g_deg[MAXN];
__device__ int      g_rowptr[MAXN + 1];
__device__ int      g_cursor[MAXN];
__device__ int      g_col[2 * MAXE];
__device__ int      g_bsum[64];
__device__ int      g_boff[64];

// ---------------- helpers ----------------
__device__ __forceinline__ void mma_f16(float* d, const unsigned* a, const unsigned* b) {
    asm volatile(
        "mma.sync.aligned.m16n8k16.row.col.f32.f16.f16.f32 "
        "{%0,%1,%2,%3}, {%4,%5,%6,%7}, {%8,%9}, {%0,%1,%2,%3};"
        : "+f"(d[0]), "+f"(d[1]), "+f"(d[2]), "+f"(d[3])
        : "r"(a[0]), "r"(a[1]), "r"(a[2]), "r"(a[3]), "r"(b[0]), "r"(b[1]));
}
__device__ __forceinline__ void cp16(unsigned smaddr, const void* g, int pred) {
    int sz = pred ? 16 : 0;
    asm volatile("cp.async.cg.shared.global [%0], [%1], 16, %2;"
                 :: "r"(smaddr), "l"(g), "r"(sz));
}
__device__ __forceinline__ void cp_commit() {
    asm volatile("cp.async.commit_group;");
}

// ---------------- K0: one-shot weight packing to fp16 (half2 along k) ----------------
__global__ void k_convw(const float* __restrict__ w1, const float* __restrict__ w2,
                        const float* __restrict__ scales)
{
    int i = blockIdx.x * blockDim.x + threadIdx.x;
    if (i < 256 * 256) {
        int k2 = i >> 8, n = i & 255;
        float s = scales[k2 >> 6];
        __half2 h = __floats2half2_rn(s * w1[(size_t)(2 * k2) * 256 + n],
                                      s * w1[(size_t)(2 * k2 + 1) * 256 + n]);
        g_w1p[i] = *(unsigned*)&h;
    }
    if (i < 128 * 128) {
        int k2 = i >> 7, n = i & 127;
        __half2 h = __floats2half2_rn(w2[(size_t)(2 * k2) * 128 + n],
                                      w2[(size_t)(2 * k2 + 1) * 128 + n]);
        g_w2p[i] = *(unsigned*)&h;
    }
}

// ---------------- K1: node prompt + per-node edge projections ----------------
__global__ void k_node(const float* __restrict__ x,
                       const float* __restrict__ nattw,   // [128,5]
                       const float* __restrict__ nattb,   // [5]
                       const float* __restrict__ eww,     // [256,5]
                       const float* __restrict__ nanch,   // [5,128]
                       int N)
{
    __shared__ float  Ws[D][16];
    __shared__ float4 An[AA][D / 4];
    int tid = threadIdx.x;
    for (int idx = tid; idx < D * 15; idx += blockDim.x) {
        int d = idx / 15, a = idx - d * 15;
        float v;
        if (a < 5)       v = nattw[d * 5 + a];
        else if (a < 10) v = eww[d * 5 + (a - 5)];
        else             v = eww[(D + d) * 5 + (a - 10)];
        Ws[d][a] = v;
    }
    for (int idx = tid; idx < AA * (D / 4); idx += blockDim.x)
        An[idx / (D / 4)][idx % (D / 4)] = ((const float4*)nanch)[idx];
    __syncthreads();

    int i = blockIdx.x * blockDim.x + tid;
    if (i >= N) return;
    const float4* xr = (const float4*)(x + (size_t)i * D);
    float acc[15];
#pragma unroll
    for (int a = 0; a < 15; a++) acc[a] = 0.f;
#pragma unroll 4
    for (int c = 0; c < D / 4; c++) {
        float4 xv = xr[c];
        float xs[4] = {xv.x, xv.y, xv.z, xv.w};
#pragma unroll
        for (int r = 0; r < 4; r++) {
            const float* wr = Ws[c * 4 + r];
#pragma unroll
            for (int a = 0; a < 15; a++) acc[a] += xs[r] * wr[a];
        }
    }
    float lg[5];
#pragma unroll
    for (int a = 0; a < 5; a++) lg[a] = acc[a] + nattb[a];
    float m = lg[0];
#pragma unroll
    for (int a = 1; a < 5; a++) m = fmaxf(m, lg[a]);
    float w[5], sum = 0.f;
#pragma unroll
    for (int a = 0; a < 5; a++) { w[a] = __expf(lg[a] - m); sum += w[a]; }
    float inv = 1.f / sum;
#pragma unroll
    for (int a = 0; a < 5; a++) w[a] *= inv;

    float4* nxr = (float4*)(g_nx + (size_t)i * D);
#pragma unroll 4
    for (int c = 0; c < D / 4; c++) {
        float4 o = xr[c];
#pragma unroll
        for (int a = 0; a < 5; a++) {
            float4 v = An[a][c];
            o.x += w[a] * v.x; o.y += w[a] * v.y; o.z += w[a] * v.z; o.w += w[a] * v.w;
        }
        nxr[c] = o;
    }
#pragma unroll
    for (int a = 0; a < 5; a++) {
        g_p[i * 5 + a] = acc[5 + a];
        g_q[i * 5 + a] = acc[10 + a];
        g_c[i * 5 + a] = 0.f;
    }
}

// ---------------- K2a: edge softmax coeffs -> scatter to g_c (critical path) ----------------
__global__ void k_ecoef(const int* __restrict__ ei,
                        const float* __restrict__ ewb,
                        int E)
{
    int e = blockIdx.x * blockDim.x + threadIdx.x;
    if (e >= E) return;
    int s = ei[e], d = ei[E + e];
    float l[5];
    float m = -1e30f;
#pragma unroll
    for (int a = 0; a < 5; a++) {
        float v = g_p[s * 5 + a] + g_q[d * 5 + a] + ewb[a];
        v = (v >= 0.f) ? v : 0.01f * v;   // leaky_relu(0.01)
        l[a] = v;
        m = fmaxf(m, v);
    }
    float sum = 0.f;
#pragma unroll
    for (int a = 0; a < 5; a++) { l[a] = __expf(l[a] - m); sum += l[a]; }
    float inv = 1.f / sum;
#pragma unroll
    for (int a = 0; a < 5; a++) {
        float v = l[a] * inv;
        atomicAdd(&g_c[s * 5 + a], v);
        atomicAdd(&g_c[d * 5 + a], v);
    }
}

// ---------------- K2b: edge prompt write (overlapped on stream B) ----------------
__global__ void k_ewrite(const int* __restrict__ ei,
                         const float* __restrict__ eanch,  // [5,128]
                         const float* __restrict__ ewb,    // [5]
                         float* __restrict__ out_ep,
                         int E)
{
    long long gt = (long long)blockIdx.x * blockDim.x + threadIdx.x;
    int e = (int)(gt >> 5);
    int lane = (int)(gt & 31);
    if (e >= E) return;
    int s = ei[e], d = ei[E + e];
    float l[5];
    float m = -1e30f;
#pragma unroll
    for (int a = 0; a < 5; a++) {
        float v = g_p[s * 5 + a] + g_q[d * 5 + a] + ewb[a];
        v = (v >= 0.f) ? v : 0.01f * v;
        l[a] = v;
        m = fmaxf(m, v);
    }
    float sum = 0.f;
#pragma unroll
    for (int a = 0; a < 5; a++) { l[a] = __expf(l[a] - m); sum += l[a]; }
    float inv = 1.f / sum;
#pragma unroll
    for (int a = 0; a < 5; a++) l[a] *= inv;

    const float4* ar = (const float4*)eanch;
    float4 o = make_float4(0.f, 0.f, 0.f, 0.f);
#pragma unroll
    for (int a = 0; a < 5; a++) {
        float4 v = ar[a * (D / 4) + lane];
        o.x += l[a] * v.x; o.y += l[a] * v.y; o.z += l[a] * v.z; o.w += l[a] * v.w;
    }
    __stcs(&((float4*)out_ep)[(size_t)e * (D / 4) + lane], o);
}

// ---------------- stream-B chain: degree count -> scan -> CSR fill ----------------
__global__ void k_zerodeg(int N)
{
    int i = blockIdx.x * blockDim.x + threadIdx.x;
    if (i < N) g_deg[i] = 0;
}

__global__ void k_deg(const int* __restrict__ ei, int E)
{
    int base = 2 * (blockIdx.x * blockDim.x + threadIdx.x);
    if (base >= E) return;
    atomicAdd(&g_deg[ei[base]], 1);
    atomicAdd(&g_deg[ei[E + base]], 1);
    if (base + 1 < E) {
        atomicAdd(&g_deg[ei[base + 1]], 1);
        atomicAdd(&g_deg[ei[E + base + 1]], 1);
    }
}

__global__ void k_scan1(int N)
{
    __shared__ int ws[32];
    int b = blockIdx.x, t = threadIdx.x;
    int i = b * 1024 + t;
    int v = (i < N) ? g_deg[i] : 0;
    int lane = t & 31, w = t >> 5;
    int s = v;
#pragma unroll
    for (int o = 1; o < 32; o <<= 1) {
        int n = __shfl_up_sync(0xffffffffu, s, o);
        if (lane >= o) s += n;
    }
    if (lane == 31) ws[w] = s;
    __syncthreads();
    if (w == 0) {
        int xv = ws[lane];
#pragma unroll
        for (int o = 1; o < 32; o <<= 1) {
            int n = __shfl_up_sync(0xffffffffu, xv, o);
            if (lane >= o) xv += n;
        }
        ws[lane] = xv;
    }
    __syncthreads();
    int incl = s + ((w > 0) ? ws[w - 1] : 0);
    if (i < N) g_rowptr[i + 1] = incl;
    if (t == 1023) g_bsum[b] = incl;
}

__global__ void k_scan2(int nb)
{
    __shared__ int sh[64];
    int t = threadIdx.x;
    int v = (t < nb) ? g_bsum[t] : 0;
    sh[t] = v;
    __syncthreads();
#pragma unroll
    for (int o = 1; o < 64; o <<= 1) {
        int a = (t >= o) ? sh[t - o] : 0;
        __syncthreads();
        sh[t] += a;
        __syncthreads();
    }
    g_boff[t] = sh[t] - v;
}

__global__ void k_scan3(int N)
{
    int i = blockIdx.x * blockDim.x + threadIdx.x;
    if (i >= N) return;
    int off = g_boff[i >> 10];
    int r = g_rowptr[i + 1] + off;
    g_rowptr[i + 1] = r;
    g_cursor[i] = r - g_deg[i];
    if (i == 0) g_rowptr[0] = 0;
}

__global__ void k_fill(const int* __restrict__ ei, int E)
{
    int base = 2 * (blockIdx.x * blockDim.x + threadIdx.x);
    if (base >= E) return;
    int s0 = ei[base], d0 = ei[E + base];
    int have2 = (base + 1 < E);
    int s1 = 0, d1 = 0;
    if (have2) { s1 = ei[base + 1]; d1 = ei[E + base + 1]; }
    int p0 = atomicAdd(&g_cursor[s0], 1);
    int p1 = atomicAdd(&g_cursor[d0], 1);
    int p2 = have2 ? atomicAdd(&g_cursor[s1], 1) : 0;
    int p3 = have2 ? atomicAdd(&g_cursor[d1], 1) : 0;
    g_col[p0] = d0;
    g_col[p1] = s0;
    if (have2) { g_col[p2] = d1; g_col[p3] = s1; }
}

// ---------------- K5: base = node_x + c @ edge_anchor (fp32 + fp16 mirror) ----------------
__global__ void k_base(const float* __restrict__ eanch, int N)
{
    __shared__ float4 An[AA][D / 4];
    int tid = threadIdx.x;
    for (int idx = tid; idx < AA * (D / 4); idx += blockDim.x)
        An[idx / (D / 4)][idx % (D / 4)] = ((const float4*)eanch)[idx];
    __syncthreads();
    int i = blockIdx.x * blockDim.x + tid;
    if (i >= N) return;
    float cv[5];
#pragma unroll
    for (int a = 0; a < 5; a++) cv[a] = g_c[i * 5 + a];
    const float4* nxr = (const float4*)(g_nx + (size_t)i * D);
    float4* br = (float4*)(g_wav[0] + (size_t)i * D);
    uint2*  hr = (uint2*)(g_wavh[0] + (size_t)i * D);
#pragma unroll 4
    for (int c = 0; c < D / 4; c++) {
        float4 o = nxr[c];
#pragma unroll
        for (int a = 0; a < 5; a++) {
            float4 v = An[a][c];
            o.x += cv[a] * v.x; o.y += cv[a] * v.y; o.z += cv[a] * v.z; o.w += cv[a] * v.w;
        }
        br[c] = o;
        __half2 h0 = __floats2half2_rn(o.x, o.y);
        __half2 h1 = __floats2half2_rn(o.z, o.w);
        uint2 hp;
        hp.x = *(unsigned*)&h0;
        hp.y = *(unsigned*)&h1;
        hr[c] = hp;
    }
}

// ---------------- K6: SpMM step, fp16 gather; fp16 output (+fp32 if more steps) ----------------
__global__ void k_spmm(int step, float hn, int N)
{
    long long gt = (long long)blockIdx.x * blockDim.x + threadIdx.x;
    int i = (int)(gt >> 5);
    int lane = (int)(gt & 31);
    if (i >= N) return;
    const uint2*  finh = (const uint2*)g_wavh[step - 1];
    const float4* fin  = (const float4*)g_wav[step - 1];
    int k = g_rowptr[i], end = g_rowptr[i + 1];
    float4 acc = make_float4(0.f, 0.f, 0.f, 0.f);
    for (; k + 4 <= end; k += 4) {
        int j0 = g_col[k], j1 = g_col[k + 1], j2 = g_col[k + 2], j3 = g_col[k + 3];
        uint2 u0 = finh[(size_t)j0 * 32 + lane];
        uint2 u1 = finh[(size_t)j1 * 32 + lane];
        uint2 u2 = finh[(size_t)j2 * 32 + lane];
        uint2 u3 = finh[(size_t)j3 * 32 + lane];
        __half2 s0 = __hadd2(*(__half2*)&u0.x, *(__half2*)&u1.x);
        __half2 s1 = __hadd2(*(__half2*)&u2.x, *(__half2*)&u3.x);
        __half2 t0 = __hadd2(*(__half2*)&u0.y, *(__half2*)&u1.y);
        __half2 t1 = __hadd2(*(__half2*)&u2.y, *(__half2*)&u3.y);
        float2 f0 = __half22float2(s0), f1 = __half22float2(s1);
        float2 f2 = __half22float2(t0), f3 = __half22float2(t1);
        acc.x += f0.x + f1.x;
        acc.y += f0.y + f1.y;
        acc.z += f2.x + f3.x;
        acc.w += f2.y + f3.y;
    }
    for (; k < end; k++) {
        int j = g_col[k];
        uint2 u = finh[(size_t)j * 32 + lane];
        float2 f0 = __half22float2(*(__half2*)&u.x);
        float2 f1 = __half22float2(*(__half2*)&u.y);
        acc.x += f0.x; acc.y += f0.y; acc.z += f1.x; acc.w += f1.y;
    }
    float4 sf = fin[(size_t)i * 32 + lane];
    float4 o;
    o.x = 0.5f * sf.x + hn * acc.x;
    o.y = 0.5f * sf.y + hn * acc.y;
    o.z = 0.5f * sf.z + hn * acc.z;
    o.w = 0.5f * sf.w + hn * acc.w;
    __half2 h0 = __floats2half2_rn(o.x, o.y);
    __half2 h1 = __floats2half2_rn(o.z, o.w);
    uint2 hp;
    hp.x = *(unsigned*)&h0;
    hp.y = *(unsigned*)&h1;
    ((uint2*)g_wavh[step])[(size_t)i * 32 + lane] = hp;
    if (step < SS)
        ((float4*)g_wav[step])[(size_t)i * 32 + lane] = o;
}

// ---------------- GEMM staging constants (fp16, half2 words) ----------------
#define A_STR2 20
#define B_STR2 136
#define A_BUF2 (128 * A_STR2)   // 2560 words
#define B_BUF2 (16 * B_STR2)    // 2176 words
#define SMEM_GEMM ((2 * A_BUF2 + 2 * B_BUF2) * 4)   // 37888 B

// ---------------- K7: fusion GEMM1 (fp16 mma, cp.async 2-stage)  h = relu(comb@W1+b1) ----------------
__global__ __launch_bounds__(256, 2) void k_gemm1(const float* __restrict__ b1, int N)
{
    extern __shared__ unsigned smem[];
    unsigned* As = smem;                // [2][A_BUF2]
    unsigned* Bs = smem + 2 * A_BUF2;   // [2][B_BUF2]
    unsigned smA = (unsigned)__cvta_generic_to_shared(As);
    unsigned smB = (unsigned)__cvta_generic_to_shared(Bs);

    int tid = threadIdx.x;
    int wid = tid >> 5, lane = tid & 31;
    int grp = lane >> 2, qid = lane & 3;
    int mw = (wid >> 2) * 64;
    int nw = (wid & 3) * 32;
    int bm0 = blockIdx.x * 128, bn0 = blockIdx.y * 128;

    float dacc[4][4][4];
#pragma unroll
    for (int i = 0; i < 4; i++)
#pragma unroll
        for (int j = 0; j < 4; j++)
#pragma unroll
            for (int r = 0; r < 4; r++) dacc[i][j][r] = 0.f;

    auto stage = [&](int kt, int buf) {
        const __half* Aseg = g_wavh[1 + (kt >> 2)];
        int kc = (kt & 3) * 32;                 // halves
#pragma unroll
        for (int v = 0; v < 2; v++) {
            int id = tid + 256 * v;             // 512 chunks
            int row = id >> 2, c = id & 3;      // 4 x 16B per row
            int gr = bm0 + row;
            unsigned dst = smA + (buf * A_BUF2 + row * A_STR2 + c * 4) * 4;
            cp16(dst, Aseg + (size_t)gr * 128 + kc + c * 8, gr < N);
        }
#pragma unroll
        for (int v = 0; v < 2; v++) {
            int id = tid + 256 * v;
            int kr = id >> 5, c = id & 31;      // 16 rows x 32 chunks
            unsigned dst = smB + (buf * B_BUF2 + kr * B_STR2 + c * 4) * 4;
            cp16(dst, g_w1p + (size_t)(kt * 16 + kr) * 256 + bn0 + c * 4, 1);
        }
        cp_commit();
    };

    stage(0, 0);
    for (int kt = 0; kt < 16; kt++) {
        int cur = kt & 1;
        if (kt + 1 < 16) {
            stage(kt + 1, cur ^ 1);
            asm volatile("cp.async.wait_group 1;");
        } else {
            asm volatile("cp.async.wait_group 0;");
        }
        __syncthreads();
        const unsigned* Ab = As + cur * A_BUF2;
        const unsigned* Bb = Bs + cur * B_BUF2;
#pragma unroll
        for (int s = 0; s < 2; s++) {           // two k16 steps per 32-k tile
            int k8h = s * 8;
            unsigned afr[4][4];
#pragma unroll
            for (int ms = 0; ms < 4; ms++) {
                int r0 = mw + ms * 16 + grp;
                afr[ms][0] = Ab[r0 * A_STR2 + k8h + qid];
                afr[ms][1] = Ab[(r0 + 8) * A_STR2 + k8h + qid];
                afr[ms][2] = Ab[r0 * A_STR2 + k8h + qid + 4];
                afr[ms][3] = Ab[(r0 + 8) * A_STR2 + k8h + qid + 4];
            }
            unsigned bfr[4][2];
#pragma unroll
            for (int ns = 0; ns < 4; ns++) {
                int c0 = nw + ns * 8 + grp;
                bfr[ns][0] = Bb[(k8h + qid) * B_STR2 + c0];
                bfr[ns][1] = Bb[(k8h + qid + 4) * B_STR2 + c0];
            }
#pragma unroll
            for (int ms = 0; ms < 4; ms++)
#pragma unroll
                for (int ns = 0; ns < 4; ns++)
                    mma_f16(dacc[ms][ns], afr[ms], bfr[ns]);
        }
        __syncthreads();
    }
#pragma unroll
    for (int ms = 0; ms < 4; ms++) {
        int gr0 = bm0 + mw + ms * 16 + grp;
#pragma unroll
        for (int ns = 0; ns < 4; ns++) {
            int gc = bn0 + nw + ns * 8 + qid * 2;
            float bz0 = b1[gc], bz1 = b1[gc + 1];
            if (gr0 < N) {
                __half2 h = __floats2half2_rn(fmaxf(dacc[ms][ns][0] + bz0, 0.f),
                                              fmaxf(dacc[ms][ns][1] + bz1, 0.f));
                g_hp[(size_t)gr0 * 128 + (gc >> 1)] = *(unsigned*)&h;
            }
            if (gr0 + 8 < N) {
                __half2 h = __floats2half2_rn(fmaxf(dacc[ms][ns][2] + bz0, 0.f),
                                              fmaxf(dacc[ms][ns][3] + bz1, 0.f));
                g_hp[(size_t)(gr0 + 8) * 128 + (gc >> 1)] = *(unsigned*)&h;
            }
        }
    }
}

// ---------------- K8: fusion GEMM2 (fp16 mma, cp.async 2-stage)  final = h @ W2 + b2 ----------------
__global__ __launch_bounds__(256, 2) void k_gemm2(const float* __restrict__ b2,
                                                  float* __restrict__ out,
                                                  int N)
{
    extern __shared__ unsigned smem[];
    unsigned* As = smem;
    unsigned* Bs = smem + 2 * A_BUF2;
    unsigned smA = (unsigned)__cvta_generic_to_shared(As);
    unsigned smB = (unsigned)__cvta_generic_to_shared(Bs);

    int tid = threadIdx.x;
    int wid = tid >> 5, lane = tid & 31;
    int grp = lane >> 2, qid = lane & 3;
    int mw = (wid >> 2) * 64;
    int nw = (wid & 3) * 32;
    int bm0 = blockIdx.x * 128;

    float dacc[4][4][4];
#pragma unroll
    for (int i = 0; i < 4; i++)
#pragma unroll
        for (int j = 0; j < 4; j++)
#pragma unroll
            for (int r = 0; r < 4; r++) dacc[i][j][r] = 0.f;

    auto stage = [&](int kt, int buf) {
#pragma unroll
        for (int v = 0; v < 2; v++) {
            int id = tid + 256 * v;
            int row = id >> 2, c = id & 3;
            int gr = bm0 + row;
            unsigned dst = smA + (buf * A_BUF2 + row * A_STR2 + c * 4) * 4;
            cp16(dst, g_hp + (size_t)gr * 128 + kt * 16 + c * 4, gr < N);
        }
#pragma unroll
        for (int v = 0; v < 2; v++) {
            int id = tid + 256 * v;
            int kr = id >> 5, c = id & 31;
            unsigned dst = smB + (buf * B_BUF2 + kr * B_STR2 + c * 4) * 4;
            cp16(dst, g_w2p + (size_t)(kt * 16 + kr) * 128 + c * 4, 1);
        }
        cp_commit();
    };

    stage(0, 0);
    for (int kt = 0; kt < 8; kt++) {
        int cur = kt & 1;
        if (kt + 1 < 8) {
            stage(kt + 1, cur ^ 1);
            asm volatile("cp.async.wait_group 1;");
        } else {
            asm volatile("cp.async.wait_group 0;");
        }
        __syncthreads();
        const unsigned* Ab = As + cur * A_BUF2;
        const unsigned* Bb = Bs + cur * B_BUF2;
#pragma unroll
        for (int s = 0; s < 2; s++) {
            int k8h = s * 8;
            unsigned afr[4][4];
#pragma unroll
            for (int ms = 0; ms < 4; ms++) {
                int r0 = mw + ms * 16 + grp;
                afr[ms][0] = Ab[r0 * A_STR2 + k8h + qid];
                afr[ms][1] = Ab[(r0 + 8) * A_STR2 + k8h + qid];
                afr[ms][2] = Ab[r0 * A_STR2 + k8h + qid + 4];
                afr[ms][3] = Ab[(r0 + 8) * A_STR2 + k8h + qid + 4];
            }
            unsigned bfr[4][2];
#pragma unroll
            for (int ns = 0; ns < 4; ns++) {
                int c0 = nw + ns * 8 + grp;
                bfr[ns][0] = Bb[(k8h + qid) * B_STR2 + c0];
                bfr[ns][1] = Bb[(k8h + qid + 4) * B_STR2 + c0];
            }
#pragma unroll
            for (int ms = 0; ms < 4; ms++)
#pragma unroll
                for (int ns = 0; ns < 4; ns++)
                    mma_f16(dacc[ms][ns], afr[ms], bfr[ns]);
        }
        __syncthreads();
    }
#pragma unroll
    for (int ms = 0; ms < 4; ms++) {
        int gr0 = bm0 + mw + ms * 16 + grp;
#pragma unroll
        for (int ns = 0; ns < 4; ns++) {
            int gc = nw + ns * 8 + qid * 2;
            float bz0 = b2[gc], bz1 = b2[gc + 1];
            if (gr0 < N) {
                float2 o;
                o.x = dacc[ms][ns][0] + bz0;
                o.y = dacc[ms][ns][1] + bz1;
                *(float2*)(out + (size_t)gr0 * 128 + gc) = o;
            }
            if (gr0 + 8 < N) {
                float2 o;
                o.x = dacc[ms][ns][2] + bz0;
                o.y = dacc[ms][ns][3] + bz1;
                *(float2*)(out + (size_t)(gr0 + 8) * 128 + gc) = o;
            }
        }
    }
}

// ---------------- host launcher: fork/join two-stream graph ----------------
extern "C" void kernel_launch(void* const* d_in, const int* in_sizes, int n_in,
                              void* d_out, int out_size)
{
    const float* x      = (const float*)d_in[0];
    const int*   ei     = (const int*)d_in[1];
    const float* nanch  = (const float*)d_in[2];
    const float* nattw  = (const float*)d_in[3];
    const float* nattb  = (const float*)d_in[4];
    const float* eanch  = (const float*)d_in[5];
    const float* eww    = (const float*)d_in[6];
    const float* ewb    = (const float*)d_in[7];
    const float* scales = (const float*)d_in[8];
    const float* fw1    = (const float*)d_in[9];
    const float* fb1    = (const float*)d_in[10];
    const float* fw2    = (const float*)d_in[11];
    const float* fb2    = (const float*)d_in[12];

    int N = in_sizes[0] / D;
    int E = in_sizes[1] / 2;
    float norm = (float)E / (float)N + 1e-6f;
    float hn = 0.5f / norm;

    float* out_final = (float*)d_out;
    float* out_ep    = out_final + (size_t)N * D;

    cudaFuncSetAttribute(k_gemm1, cudaFuncAttributeMaxDynamicSharedMemorySize, SMEM_GEMM);
    cudaFuncSetAttribute(k_gemm2, cudaFuncAttributeMaxDynamicSharedMemorySize, SMEM_GEMM);

    // fork a side stream (depends only on edge_index + later on k_node via event)
    cudaStream_t sB;
    cudaStreamCreateWithFlags(&sB, cudaStreamNonBlocking);
    cudaEvent_t evFork, evNode, evCSR, evB2;
    cudaEventCreateWithFlags(&evFork, cudaEventDisableTiming);
    cudaEventCreateWithFlags(&evNode, cudaEventDisableTiming);
    cudaEventCreateWithFlags(&evCSR,  cudaEventDisableTiming);
    cudaEventCreateWithFlags(&evB2,   cudaEventDisableTiming);

    cudaEventRecord(evFork, 0);
    cudaStreamWaitEvent(sB, evFork, 0);

    // stream B part 1: CSR build
    k_zerodeg<<<(N + 255) / 256, 256, 0, sB>>>(N);
    k_deg<<<(E / 2 + 256) / 256, 256, 0, sB>>>(ei, E);
    int nb = (N + 1023) / 1024;
    k_scan1<<<nb, 1024, 0, sB>>>(N);
    k_scan2<<<1, 64, 0, sB>>>(nb);
    k_scan3<<<(N + 255) / 256, 256, 0, sB>>>(N);
    k_fill<<<(E / 2 + 256) / 256, 256, 0, sB>>>(ei, E);
    cudaEventRecord(evCSR, sB);

    // stream 0: weights + node chain (coeff scatter only on critical path)
    k_convw<<<(256 * 256 + 255) / 256, 256>>>(fw1, fw2, scales);
    k_node<<<(N + 255) / 256, 256>>>(x, nattw, nattb, eww, nanch, N);
    cudaEventRecord(evNode, 0);
    k_ecoef<<<(E + 255) / 256, 256>>>(ei, ewb, E);
    k_base<<<(N + 255) / 256, 256>>>(eanch, N);

    // stream B part 2: edge_prompt write, overlapped with SpMM chain
    cudaStreamWaitEvent(sB, evNode, 0);
    long long et = (long long)E * 32;
    k_ewrite<<<(unsigned)((et + 255) / 256), 256, 0, sB>>>(ei, eanch, ewb, out_ep, E);
    cudaEventRecord(evB2, sB);

    // stream 0: join CSR, run SpMM + GEMMs
    cudaStreamWaitEvent(0, evCSR, 0);
    long long nt = (long long)N * 32;
    unsigned nblk = (unsigned)((nt + 255) / 256);
    for (int s = 1; s <= SS; s++)
        k_spmm<<<nblk, 256>>>(s, hn, N);

    dim3 g1((N + 127) / 128, 2);
    k_gemm1<<<g1, 256, SMEM_GEMM>>>(fb1, N);
    dim3 g2((N + 127) / 128, 1);
    k_gemm2<<<g2, 256, SMEM_GEMM>>>(fb2, out_final, N);

    // terminal join so all forked work is inside the captured graph
    cudaStreamWaitEvent(0, evB2, 0);
    // NOTE: sB/events intentionally not destroyed (mid-capture destruction is
    // illegal; kernel_launch runs only twice, leak is bounded).
}

// round 10
// speedup vs baseline: 1.2407x; 1.2407x over previous
#include <cuda_runtime.h>
#include <cuda_fp16.h>
#include <cstdint>

#define D 128
#define AA 5
#define SS 4
#define MAXN 50000
#define MAXE 640000

// ---------------- static scratch (no runtime allocation allowed) ----------------
__device__ float    g_nx[(size_t)MAXN * D];              // node_x
__device__ __half   g_wavh[SS + 1][(size_t)MAXN * D];    // fp16 levels 0..4 (gather + self + GEMM A)
__device__ unsigned g_w1p[256 * 256];                    // W1 packed half2-along-k, scales folded
__device__ unsigned g_w2p[128 * 128];                    // W2 packed half2-along-k
__device__ unsigned g_hp[(size_t)MAXN * 128];            // hidden packed half2 [N, 256 halves]
__device__ float    g_p[MAXN * AA];
__device__ float    g_q[MAXN * AA];
__device__ float    g_c[MAXN * AA];
__device__ int      g_deg[MAXN];
__device__ int      g_rowptr[MAXN + 1];
__device__ int      g_cursor[MAXN];
__device__ int      g_col[2 * MAXE];
__device__ int      g_bsum[64];
__device__ int      g_boff[64];

// ---------------- helpers ----------------
__device__ __forceinline__ void mma_f16(float* d, const unsigned* a, const unsigned* b) {
    asm volatile(
        "mma.sync.aligned.m16n8k16.row.col.f32.f16.f16.f32 "
        "{%0,%1,%2,%3}, {%4,%5,%6,%7}, {%8,%9}, {%0,%1,%2,%3};"
        : "+f"(d[0]), "+f"(d[1]), "+f"(d[2]), "+f"(d[3])
        : "r"(a[0]), "r"(a[1]), "r"(a[2]), "r"(a[3]), "r"(b[0]), "r"(b[1]));
}
__device__ __forceinline__ void cp16(unsigned smaddr, const void* g, int pred) {
    int sz = pred ? 16 : 0;
    asm volatile("cp.async.cg.shared.global [%0], [%1], 16, %2;"
                 :: "r"(smaddr), "l"(g), "r"(sz));
}
__device__ __forceinline__ void cp_commit() {
    asm volatile("cp.async.commit_group;");
}

// ---------------- K0: one-shot weight packing to fp16 (half2 along k) ----------------
__global__ void k_convw(const float* __restrict__ w1, const float* __restrict__ w2,
                        const float* __restrict__ scales)
{
    int i = blockIdx.x * blockDim.x + threadIdx.x;
    if (i < 256 * 256) {
        int k2 = i >> 8, n = i & 255;
        float s = scales[k2 >> 6];
        __half2 h = __floats2half2_rn(s * w1[(size_t)(2 * k2) * 256 + n],
                                      s * w1[(size_t)(2 * k2 + 1) * 256 + n]);
        g_w1p[i] = *(unsigned*)&h;
    }
    if (i < 128 * 128) {
        int k2 = i >> 7, n = i & 127;
        __half2 h = __floats2half2_rn(w2[(size_t)(2 * k2) * 128 + n],
                                      w2[(size_t)(2 * k2 + 1) * 128 + n]);
        g_w2p[i] = *(unsigned*)&h;
    }
}

// ---------------- K1: node prompt + per-node edge projections ----------------
__global__ void k_node(const float* __restrict__ x,
                       const float* __restrict__ nattw,   // [128,5]
                       const float* __restrict__ nattb,   // [5]
                       const float* __restrict__ eww,     // [256,5]
                       const float* __restrict__ nanch,   // [5,128]
                       int N)
{
    __shared__ float  Ws[D][16];
    __shared__ float4 An[AA][D / 4];
    int tid = threadIdx.x;
    for (int idx = tid; idx < D * 15; idx += blockDim.x) {
        int d = idx / 15, a = idx - d * 15;
        float v;
        if (a < 5)       v = nattw[d * 5 + a];
        else if (a < 10) v = eww[d * 5 + (a - 5)];
        else             v = eww[(D + d) * 5 + (a - 10)];
        Ws[d][a] = v;
    }
    for (int idx = tid; idx < AA * (D / 4); idx += blockDim.x)
        An[idx / (D / 4)][idx % (D / 4)] = ((const float4*)nanch)[idx];
    __syncthreads();

    int i = blockIdx.x * blockDim.x + tid;
    if (i >= N) return;
    const float4* xr = (const float4*)(x + (size_t)i * D);
    float acc[15];
#pragma unroll
    for (int a = 0; a < 15; a++) acc[a] = 0.f;
#pragma unroll 4
    for (int c = 0; c < D / 4; c++) {
        float4 xv = xr[c];
        float xs[4] = {xv.x, xv.y, xv.z, xv.w};
#pragma unroll
        for (int r = 0; r < 4; r++) {
            const float* wr = Ws[c * 4 + r];
#pragma unroll
            for (int a = 0; a < 15; a++) acc[a] += xs[r] * wr[a];
        }
    }
    float lg[5];
#pragma unroll
    for (int a = 0; a < 5; a++) lg[a] = acc[a] + nattb[a];
    float m = lg[0];
#pragma unroll
    for (int a = 1; a < 5; a++) m = fmaxf(m, lg[a]);
    float w[5], sum = 0.f;
#pragma unroll
    for (int a = 0; a < 5; a++) { w[a] = __expf(lg[a] - m); sum += w[a]; }
    float inv = 1.f / sum;
#pragma unroll
    for (int a = 0; a < 5; a++) w[a] *= inv;

    float4* nxr = (float4*)(g_nx + (size_t)i * D);
#pragma unroll 4
    for (int c = 0; c < D / 4; c++) {
        float4 o = xr[c];
#pragma unroll
        for (int a = 0; a < 5; a++) {
            float4 v = An[a][c];
            o.x += w[a] * v.x; o.y += w[a] * v.y; o.z += w[a] * v.z; o.w += w[a] * v.w;
        }
        nxr[c] = o;
    }
#pragma unroll
    for (int a = 0; a < 5; a++) {
        g_p[i * 5 + a] = acc[5 + a];
        g_q[i * 5 + a] = acc[10 + a];
        g_c[i * 5 + a] = 0.f;
    }
}

// ---------------- K2: edge prompt + coeff scatter (round-7 fused form) ----------------
__global__ void k_edge(const int* __restrict__ ei,
                       const float* __restrict__ eanch,  // [5,128]
                       const float* __restrict__ ewb,    // [5]
                       float* __restrict__ out_ep,
                       int E)
{
    long long gt = (long long)blockIdx.x * blockDim.x + threadIdx.x;
    int e = (int)(gt >> 5);
    int lane = (int)(gt & 31);
    if (e >= E) return;
    int s = ei[e], d = ei[E + e];
    float l[5];
    float m = -1e30f;
#pragma unroll
    for (int a = 0; a < 5; a++) {
        float v = g_p[s * 5 + a] + g_q[d * 5 + a] + ewb[a];
        v = (v >= 0.f) ? v : 0.01f * v;   // leaky_relu(0.01)
        l[a] = v;
        m = fmaxf(m, v);
    }
    float sum = 0.f;
#pragma unroll
    for (int a = 0; a < 5; a++) { l[a] = __expf(l[a] - m); sum += l[a]; }
    float inv = 1.f / sum;
#pragma unroll
    for (int a = 0; a < 5; a++) l[a] *= inv;

    const float4* ar = (const float4*)eanch;
    float4 o = make_float4(0.f, 0.f, 0.f, 0.f);
#pragma unroll
    for (int a = 0; a < 5; a++) {
        float4 v = ar[a * (D / 4) + lane];
        o.x += l[a] * v.x; o.y += l[a] * v.y; o.z += l[a] * v.z; o.w += l[a] * v.w;
    }
    __stcs(&((float4*)out_ep)[(size_t)e * (D / 4) + lane], o);

    if (lane < 5)                    atomicAdd(&g_c[s * 5 + lane], l[lane]);
    else if (lane >= 8 && lane < 13) atomicAdd(&g_c[d * 5 + (lane - 8)], l[lane - 8]);
}

// ---------------- stream-B chain: degree count -> scan -> CSR fill ----------------
__global__ void k_zerodeg(int N)
{
    int i = blockIdx.x * blockDim.x + threadIdx.x;
    if (i < N) g_deg[i] = 0;
}

__global__ void k_deg(const int* __restrict__ ei, int E)
{
    int base = 2 * (blockIdx.x * blockDim.x + threadIdx.x);
    if (base >= E) return;
    atomicAdd(&g_deg[ei[base]], 1);
    atomicAdd(&g_deg[ei[E + base]], 1);
    if (base + 1 < E) {
        atomicAdd(&g_deg[ei[base + 1]], 1);
        atomicAdd(&g_deg[ei[E + base + 1]], 1);
    }
}

__global__ void k_scan1(int N)
{
    __shared__ int ws[32];
    int b = blockIdx.x, t = threadIdx.x;
    int i = b * 1024 + t;
    int v = (i < N) ? g_deg[i] : 0;
    int lane = t & 31, w = t >> 5;
    int s = v;
#pragma unroll
    for (int o = 1; o < 32; o <<= 1) {
        int n = __shfl_up_sync(0xffffffffu, s, o);
        if (lane >= o) s += n;
    }
    if (lane == 31) ws[w] = s;
    __syncthreads();
    if (w == 0) {
        int xv = ws[lane];
#pragma unroll
        for (int o = 1; o < 32; o <<= 1) {
            int n = __shfl_up_sync(0xffffffffu, xv, o);
            if (lane >= o) xv += n;
        }
        ws[lane] = xv;
    }
    __syncthreads();
    int incl = s + ((w > 0) ? ws[w - 1] : 0);
    if (i < N) g_rowptr[i + 1] = incl;
    if (t == 1023) g_bsum[b] = incl;
}

__global__ void k_scan2(int nb)
{
    __shared__ int sh[64];
    int t = threadIdx.x;
    int v = (t < nb) ? g_bsum[t] : 0;
    sh[t] = v;
    __syncthreads();
#pragma unroll
    for (int o = 1; o < 64; o <<= 1) {
        int a = (t >= o) ? sh[t - o] : 0;
        __syncthreads();
        sh[t] += a;
        __syncthreads();
    }
    g_boff[t] = sh[t] - v;
}

__global__ void k_scan3(int N)
{
    int i = blockIdx.x * blockDim.x + threadIdx.x;
    if (i >= N) return;
    int off = g_boff[i >> 10];
    int r = g_rowptr[i + 1] + off;
    g_rowptr[i + 1] = r;
    g_cursor[i] = r - g_deg[i];
    if (i == 0) g_rowptr[0] = 0;
}

__global__ void k_fill(const int* __restrict__ ei, int E)
{
    int base = 2 * (blockIdx.x * blockDim.x + threadIdx.x);
    if (base >= E) return;
    int s0 = ei[base], d0 = ei[E + base];
    int have2 = (base + 1 < E);
    int s1 = 0, d1 = 0;
    if (have2) { s1 = ei[base + 1]; d1 = ei[E + base + 1]; }
    int p0 = atomicAdd(&g_cursor[s0], 1);
    int p1 = atomicAdd(&g_cursor[d0], 1);
    int p2 = have2 ? atomicAdd(&g_cursor[s1], 1) : 0;
    int p3 = have2 ? atomicAdd(&g_cursor[d1], 1) : 0;
    g_col[p0] = d0;
    g_col[p1] = s0;
    if (have2) { g_col[p2] = d1; g_col[p3] = s1; }
}

// ---------------- K5: base = node_x + c @ edge_anchor (fp16 only) ----------------
__global__ void k_base(const float* __restrict__ eanch, int N)
{
    __shared__ float4 An[AA][D / 4];
    int tid = threadIdx.x;
    for (int idx = tid; idx < AA * (D / 4); idx += blockDim.x)
        An[idx / (D / 4)][idx % (D / 4)] = ((const float4*)eanch)[idx];
    __syncthreads();
    int i = blockIdx.x * blockDim.x + tid;
    if (i >= N) return;
    float cv[5];
#pragma unroll
    for (int a = 0; a < 5; a++) cv[a] = g_c[i * 5 + a];
    const float4* nxr = (const float4*)(g_nx + (size_t)i * D);
    uint2* hr = (uint2*)(g_wavh[0] + (size_t)i * D);
#pragma unroll 4
    for (int c = 0; c < D / 4; c++) {
        float4 o = nxr[c];
#pragma unroll
        for (int a = 0; a < 5; a++) {
            float4 v = An[a][c];
            o.x += cv[a] * v.x; o.y += cv[a] * v.y; o.z += cv[a] * v.z; o.w += cv[a] * v.w;
        }
        __half2 h0 = __floats2half2_rn(o.x, o.y);
        __half2 h1 = __floats2half2_rn(o.z, o.w);
        uint2 hp;
        hp.x = *(unsigned*)&h0;
        hp.y = *(unsigned*)&h1;
        hr[c] = hp;
    }
}

// ---------------- K6: SpMM step, all-fp16 state ----------------
__global__ void k_spmm(int step, float hn, int N)
{
    long long gt = (long long)blockIdx.x * blockDim.x + threadIdx.x;
    int i = (int)(gt >> 5);
    int lane = (int)(gt & 31);
    if (i >= N) return;
    const uint2* finh = (const uint2*)g_wavh[step - 1];
    int k = g_rowptr[i], end = g_rowptr[i + 1];
    float4 acc = make_float4(0.f, 0.f, 0.f, 0.f);
    for (; k + 4 <= end; k += 4) {
        int j0 = g_col[k], j1 = g_col[k + 1], j2 = g_col[k + 2], j3 = g_col[k + 3];
        uint2 u0 = finh[(size_t)j0 * 32 + lane];
        uint2 u1 = finh[(size_t)j1 * 32 + lane];
        uint2 u2 = finh[(size_t)j2 * 32 + lane];
        uint2 u3 = finh[(size_t)j3 * 32 + lane];
        __half2 s0 = __hadd2(*(__half2*)&u0.x, *(__half2*)&u1.x);
        __half2 s1 = __hadd2(*(__half2*)&u2.x, *(__half2*)&u3.x);
        __half2 t0 = __hadd2(*(__half2*)&u0.y, *(__half2*)&u1.y);
        __half2 t1 = __hadd2(*(__half2*)&u2.y, *(__half2*)&u3.y);
        float2 f0 = __half22float2(s0), f1 = __half22float2(s1);
        float2 f2 = __half22float2(t0), f3 = __half22float2(t1);
        acc.x += f0.x + f1.x;
        acc.y += f0.y + f1.y;
        acc.z += f2.x + f3.x;
        acc.w += f2.y + f3.y;
    }
    for (; k < end; k++) {
        int j = g_col[k];
        uint2 u = finh[(size_t)j * 32 + lane];
        float2 f0 = __half22float2(*(__half2*)&u.x);
        float2 f1 = __half22float2(*(__half2*)&u.y);
        acc.x += f0.x; acc.y += f0.y; acc.z += f1.x; acc.w += f1.y;
    }
    uint2 us = finh[(size_t)i * 32 + lane];
    float2 sf0 = __half22float2(*(__half2*)&us.x);
    float2 sf1 = __half22float2(*(__half2*)&us.y);
    float4 o;
    o.x = 0.5f * sf0.x + hn * acc.x;
    o.y = 0.5f * sf0.y + hn * acc.y;
    o.z = 0.5f * sf1.x + hn * acc.z;
    o.w = 0.5f * sf1.y + hn * acc.w;
    __half2 h0 = __floats2half2_rn(o.x, o.y);
    __half2 h1 = __floats2half2_rn(o.z, o.w);
    uint2 hp;
    hp.x = *(unsigned*)&h0;
    hp.y = *(unsigned*)&h1;
    ((uint2*)g_wavh[step])[(size_t)i * 32 + lane] = hp;
}

// ---------------- GEMM staging constants (fp16, half2 words) ----------------
#define A_STR2 20
#define B_STR2 136
#define A_BUF2 (128 * A_STR2)   // 2560 words
#define B_BUF2 (16 * B_STR2)    // 2176 words
#define SMEM_GEMM ((2 * A_BUF2 + 2 * B_BUF2) * 4)   // 37888 B

// ---------------- K7: fusion GEMM1 (fp16 mma, cp.async 2-stage)  h = relu(comb@W1+b1) ----------------
__global__ __launch_bounds__(256, 2) void k_gemm1(const float* __restrict__ b1, int N)
{
    extern __shared__ unsigned smem[];
    unsigned* As = smem;                // [2][A_BUF2]
    unsigned* Bs = smem + 2 * A_BUF2;   // [2][B_BUF2]
    unsigned smA = (unsigned)__cvta_generic_to_shared(As);
    unsigned smB = (unsigned)__cvta_generic_to_shared(Bs);

    int tid = threadIdx.x;
    int wid = tid >> 5, lane = tid & 31;
    int grp = lane >> 2, qid = lane & 3;
    int mw = (wid >> 2) * 64;
    int nw = (wid & 3) * 32;
    int bm0 = blockIdx.x * 128, bn0 = blockIdx.y * 128;

    float dacc[4][4][4];
#pragma unroll
    for (int i = 0; i < 4; i++)
#pragma unroll
        for (int j = 0; j < 4; j++)
#pragma unroll
            for (int r = 0; r < 4; r++) dacc[i][j][r] = 0.f;

    auto stage = [&](int kt, int buf) {
        const __half* Aseg = g_wavh[1 + (kt >> 2)];
        int kc = (kt & 3) * 32;                 // halves
#pragma unroll
        for (int v = 0; v < 2; v++) {
            int id = tid + 256 * v;             // 512 chunks
            int row = id >> 2, c = id & 3;      // 4 x 16B per row
            int gr = bm0 + row;
            unsigned dst = smA + (buf * A_BUF2 + row * A_STR2 + c * 4) * 4;
            cp16(dst, Aseg + (size_t)gr * 128 + kc + c * 8, gr < N);
        }
#pragma unroll
        for (int v = 0; v < 2; v++) {
            int id = tid + 256 * v;
            int kr = id >> 5, c = id & 31;      // 16 rows x 32 chunks
            unsigned dst = smB + (buf * B_BUF2 + kr * B_STR2 + c * 4) * 4;
            cp16(dst, g_w1p + (size_t)(kt * 16 + kr) * 256 + bn0 + c * 4, 1);
        }
        cp_commit();
    };

    stage(0, 0);
    for (int kt = 0; kt < 16; kt++) {
        int cur = kt & 1;
        if (kt + 1 < 16) {
            stage(kt + 1, cur ^ 1);
            asm volatile("cp.async.wait_group 1;");
        } else {
            asm volatile("cp.async.wait_group 0;");
        }
        __syncthreads();
        const unsigned* Ab = As + cur * A_BUF2;
        const unsigned* Bb = Bs + cur * B_BUF2;
#pragma unroll
        for (int s = 0; s < 2; s++) {           // two k16 steps per 32-k tile
            int k8h = s * 8;
            unsigned afr[4][4];
#pragma unroll
            for (int ms = 0; ms < 4; ms++) {
                int r0 = mw + ms * 16 + grp;
                afr[ms][0] = Ab[r0 * A_STR2 + k8h + qid];
                afr[ms][1] = Ab[(r0 + 8) * A_STR2 + k8h + qid];
                afr[ms][2] = Ab[r0 * A_STR2 + k8h + qid + 4];
                afr[ms][3] = Ab[(r0 + 8) * A_STR2 + k8h + qid + 4];
            }
            unsigned bfr[4][2];
#pragma unroll
            for (int ns = 0; ns < 4; ns++) {
                int c0 = nw + ns * 8 + grp;
                bfr[ns][0] = Bb[(k8h + qid) * B_STR2 + c0];
                bfr[ns][1] = Bb[(k8h + qid + 4) * B_STR2 + c0];
            }
#pragma unroll
            for (int ms = 0; ms < 4; ms++)
#pragma unroll
                for (int ns = 0; ns < 4; ns++)
                    mma_f16(dacc[ms][ns], afr[ms], bfr[ns]);
        }
        __syncthreads();
    }
#pragma unroll
    for (int ms = 0; ms < 4; ms++) {
        int gr0 = bm0 + mw + ms * 16 + grp;
#pragma unroll
        for (int ns = 0; ns < 4; ns++) {
            int gc = bn0 + nw + ns * 8 + qid * 2;
            float bz0 = b1[gc], bz1 = b1[gc + 1];
            if (gr0 < N) {
                __half2 h = __floats2half2_rn(fmaxf(dacc[ms][ns][0] + bz0, 0.f),
                                              fmaxf(dacc[ms][ns][1] + bz1, 0.f));
                g_hp[(size_t)gr0 * 128 + (gc >> 1)] = *(unsigned*)&h;
            }
            if (gr0 + 8 < N) {
                __half2 h = __floats2half2_rn(fmaxf(dacc[ms][ns][2] + bz0, 0.f),
                                              fmaxf(dacc[ms][ns][3] + bz1, 0.f));
                g_hp[(size_t)(gr0 + 8) * 128 + (gc >> 1)] = *(unsigned*)&h;
            }
        }
    }
}

// ---------------- K8: fusion GEMM2 (fp16 mma, cp.async 2-stage)  final = h @ W2 + b2 ----------------
__global__ __launch_bounds__(256, 2) void k_gemm2(const float* __restrict__ b2,
                                                  float* __restrict__ out,
                                                  int N)
{
    extern __shared__ unsigned smem[];
    unsigned* As = smem;
    unsigned* Bs = smem + 2 * A_BUF2;
    unsigned smA = (unsigned)__cvta_generic_to_shared(As);
    unsigned smB = (unsigned)__cvta_generic_to_shared(Bs);

    int tid = threadIdx.x;
    int wid = tid >> 5, lane = tid & 31;
    int grp = lane >> 2, qid = lane & 3;
    int mw = (wid >> 2) * 64;
    int nw = (wid & 3) * 32;
    int bm0 = blockIdx.x * 128;

    float dacc[4][4][4];
#pragma unroll
    for (int i = 0; i < 4; i++)
#pragma unroll
        for (int j = 0; j < 4; j++)
#pragma unroll
            for (int r = 0; r < 4; r++) dacc[i][j][r] = 0.f;

    auto stage = [&](int kt, int buf) {
#pragma unroll
        for (int v = 0; v < 2; v++) {
            int id = tid + 256 * v;
            int row = id >> 2, c = id & 3;
            int gr = bm0 + row;
            unsigned dst = smA + (buf * A_BUF2 + row * A_STR2 + c * 4) * 4;
            cp16(dst, g_hp + (size_t)gr * 128 + kt * 16 + c * 4, gr < N);
        }
#pragma unroll
        for (int v = 0; v < 2; v++) {
            int id = tid + 256 * v;
            int kr = id >> 5, c = id & 31;
            unsigned dst = smB + (buf * B_BUF2 + kr * B_STR2 + c * 4) * 4;
            cp16(dst, g_w2p + (size_t)(kt * 16 + kr) * 128 + c * 4, 1);
        }
        cp_commit();
    };

    stage(0, 0);
    for (int kt = 0; kt < 8; kt++) {
        int cur = kt & 1;
        if (kt + 1 < 8) {
            stage(kt + 1, cur ^ 1);
            asm volatile("cp.async.wait_group 1;");
        } else {
            asm volatile("cp.async.wait_group 0;");
        }
        __syncthreads();
        const unsigned* Ab = As + cur * A_BUF2;
        const unsigned* Bb = Bs + cur * B_BUF2;
#pragma unroll
        for (int s = 0; s < 2; s++) {
            int k8h = s * 8;
            unsigned afr[4][4];
#pragma unroll
            for (int ms = 0; ms < 4; ms++) {
                int r0 = mw + ms * 16 + grp;
                afr[ms][0] = Ab[r0 * A_STR2 + k8h + qid];
                afr[ms][1] = Ab[(r0 + 8) * A_STR2 + k8h + qid];
                afr[ms][2] = Ab[r0 * A_STR2 + k8h + qid + 4];
                afr[ms][3] = Ab[(r0 + 8) * A_STR2 + k8h + qid + 4];
            }
            unsigned bfr[4][2];
#pragma unroll
            for (int ns = 0; ns < 4; ns++) {
                int c0 = nw + ns * 8 + grp;
                bfr[ns][0] = Bb[(k8h + qid) * B_STR2 + c0];
                bfr[ns][1] = Bb[(k8h + qid + 4) * B_STR2 + c0];
            }
#pragma unroll
            for (int ms = 0; ms < 4; ms++)
#pragma unroll
                for (int ns = 0; ns < 4; ns++)
                    mma_f16(dacc[ms][ns], afr[ms], bfr[ns]);
        }
        __syncthreads();
    }
#pragma unroll
    for (int ms = 0; ms < 4; ms++) {
        int gr0 = bm0 + mw + ms * 16 + grp;
#pragma unroll
        for (int ns = 0; ns < 4; ns++) {
            int gc = nw + ns * 8 + qid * 2;
            float bz0 = b2[gc], bz1 = b2[gc + 1];
            if (gr0 < N) {
                float2 o;
                o.x = dacc[ms][ns][0] + bz0;
                o.y = dacc[ms][ns][1] + bz1;
                *(float2*)(out + (size_t)gr0 * 128 + gc) = o;
            }
            if (gr0 + 8 < N) {
                float2 o;
                o.x = dacc[ms][ns][2] + bz0;
                o.y = dacc[ms][ns][3] + bz1;
                *(float2*)(out + (size_t)(gr0 + 8) * 128 + gc) = o;
            }
        }
    }
}

// ---------------- host launcher: round-7 fork/join structure ----------------
extern "C" void kernel_launch(void* const* d_in, const int* in_sizes, int n_in,
                              void* d_out, int out_size)
{
    const float* x      = (const float*)d_in[0];
    const int*   ei     = (const int*)d_in[1];
    const float* nanch  = (const float*)d_in[2];
    const float* nattw  = (const float*)d_in[3];
    const float* nattb  = (const float*)d_in[4];
    const float* eanch  = (const float*)d_in[5];
    const float* eww    = (const float*)d_in[6];
    const float* ewb    = (const float*)d_in[7];
    const float* scales = (const float*)d_in[8];
    const float* fw1    = (const float*)d_in[9];
    const float* fb1    = (const float*)d_in[10];
    const float* fw2    = (const float*)d_in[11];
    const float* fb2    = (const float*)d_in[12];

    int N = in_sizes[0] / D;
    int E = in_sizes[1] / 2;
    float norm = (float)E / (float)N + 1e-6f;
    float hn = 0.5f / norm;

    float* out_final = (float*)d_out;
    float* out_ep    = out_final + (size_t)N * D;

    cudaFuncSetAttribute(k_gemm1, cudaFuncAttributeMaxDynamicSharedMemorySize, SMEM_GEMM);
    cudaFuncSetAttribute(k_gemm2, cudaFuncAttributeMaxDynamicSharedMemorySize, SMEM_GEMM);

    // fork a side stream for the CSR chain + weight conversion
    cudaStream_t sB;
    cudaStreamCreateWithFlags(&sB, cudaStreamNonBlocking);
    cudaEvent_t evFork, evJoin;
    cudaEventCreateWithFlags(&evFork, cudaEventDisableTiming);
    cudaEventCreateWithFlags(&evJoin, cudaEventDisableTiming);

    cudaEventRecord(evFork, 0);
    cudaStreamWaitEvent(sB, evFork, 0);

    // stream B: weight packing + deg -> scan -> fill (CSR ready)
    k_convw<<<(256 * 256 + 255) / 256, 256, 0, sB>>>(fw1, fw2, scales);
    k_zerodeg<<<(N + 255) / 256, 256, 0, sB>>>(N);
    k_deg<<<(E / 2 + 256) / 256, 256, 0, sB>>>(ei, E);
    int nb = (N + 1023) / 1024;
    k_scan1<<<nb, 1024, 0, sB>>>(N);
    k_scan2<<<1, 64, 0, sB>>>(nb);
    k_scan3<<<(N + 255) / 256, 256, 0, sB>>>(N);
    k_fill<<<(E / 2 + 256) / 256, 256, 0, sB>>>(ei, E);
    cudaEventRecord(evJoin, sB);

    // stream 0: node chain
    k_node<<<(N + 255) / 256, 256>>>(x, nattw, nattb, eww, nanch, N);
    long long et = (long long)E * 32;
    k_edge<<<(unsigned)((et + 255) / 256), 256>>>(ei, eanch, ewb, out_ep, E);
    k_base<<<(N + 255) / 256, 256>>>(eanch, N);

    // join: SpMM needs CSR (B) and base (0)
    cudaStreamWaitEvent(0, evJoin, 0);

    long long nt = (long long)N * 32;
    unsigned nblk = (unsigned)((nt + 255) / 256);
    for (int s = 1; s <= SS; s++)
        k_spmm<<<nblk, 256>>>(s, hn, N);

    dim3 g1((N + 127) / 128, 2);
    k_gemm1<<<g1, 256, SMEM_GEMM>>>(fb1, N);
    dim3 g2((N + 127) / 128, 1);
    k_gemm2<<<g2, 256, SMEM_GEMM>>>(fb2, out_final, N);
    // NOTE: sB/events intentionally not destroyed (mid-capture destruction is
    // illegal; kernel_launch runs only twice, leak is bounded).
}